// round 7
// baseline (speedup 1.0000x reference)
#include <cuda_runtime.h>
#include <cstdint>
#include <cstddef>

#define B_  2
#define S_  4096
#define D_  512
#define H_  8
#define DK_ 64

// Scratch for pre-projection attention output (alloc-free rule).
__device__ float g_attn[(size_t)B_ * S_ * D_];

__device__ __forceinline__ float to_tf32(float x) {
    float r;
    asm("cvt.rna.tf32.f32 %0, %1;" : "=f"(r) : "f"(x));
    return r;
}

// D = A*B + D, tf32 m16n8k8 (base sm_103-legal; runs on tensor pipe).
__device__ __forceinline__ void mma_tf32(float c[4], const uint32_t a[4],
                                         uint32_t b0, uint32_t b1) {
    asm volatile(
        "mma.sync.aligned.m16n8k8.row.col.f32.tf32.tf32.f32 "
        "{%0,%1,%2,%3}, {%4,%5,%6,%7}, {%8,%9}, {%0,%1,%2,%3};"
        : "+f"(c[0]), "+f"(c[1]), "+f"(c[2]), "+f"(c[3])
        : "r"(a[0]), "r"(a[1]), "r"(a[2]), "r"(a[3]), "r"(b0), "r"(b1));
}

// Shared-memory strides (floats), conflict-free for the fragment patterns:
// K/P stride 68 -> bank = (4g+t) distinct; V/W stride 72 -> bank = (8t+g) distinct.
#define KS_STRIDE 68
#define VS_STRIDE 72
#define PS_STRIDE 68
#define SMEM_FLOATS (64 * KS_STRIDE + 64 * VS_STRIDE + 128 * PS_STRIDE)

#define NKT (S_ / 64)

// ---------------------------------------------------------------------------
// tf32 warp-MMA flash attention (no-max softmax, O resident in registers).
// CTA = (b, h, 128-query tile). 4 warps; warp owns 32 query rows (2 m-tiles).
// ---------------------------------------------------------------------------
__global__ __launch_bounds__(128, 3)
void attn_kernel(const float* __restrict__ Q,
                 const float* __restrict__ K,
                 const float* __restrict__ V)
{
    extern __shared__ float smem[];
    float* Ks = smem;                                   // [64][68]
    float* Vs = smem + 64 * KS_STRIDE;                  // [64][72]
    float* Ps = smem + 64 * KS_STRIDE + 64 * VS_STRIDE; // [128][68]

    const int tid  = threadIdx.x;
    const int warp = tid >> 5;
    const int lane = tid & 31;
    const int g    = lane >> 2;
    const int t    = lane & 3;
    const int qt   = blockIdx.x;  // 0..31
    const int bh   = blockIdx.y;  // 0..15
    const int b    = bh >> 3, h = bh & 7;

    // ---- stage Q tile into Ps (scaled 1/8, tf32 RN), then to frags ----
    const float* qb = Q + ((size_t)(b * S_ + qt * 128)) * D_ + h * DK_;
    for (int i = tid; i < 128 * 16; i += 128) {
        int r = i >> 4, c = (i & 15) << 2;
        float4 x = *(const float4*)(qb + (size_t)r * D_ + c);
        x.x = to_tf32(x.x * 0.125f);
        x.y = to_tf32(x.y * 0.125f);
        x.z = to_tf32(x.z * 0.125f);
        x.w = to_tf32(x.w * 0.125f);
        *(float4*)(Ps + r * PS_STRIDE + c) = x;
    }
    __syncthreads();

    uint32_t qa[2][8][4];   // Q A-fragments, resident all kernel
#pragma unroll
    for (int mt = 0; mt < 2; mt++) {
        const int r0 = warp * 32 + mt * 16 + g;
#pragma unroll
        for (int ks = 0; ks < 8; ks++) {
            const int c0 = ks * 8 + t;
            qa[mt][ks][0] = __float_as_uint(Ps[(r0    ) * PS_STRIDE + c0    ]);
            qa[mt][ks][1] = __float_as_uint(Ps[(r0 + 8) * PS_STRIDE + c0    ]);
            qa[mt][ks][2] = __float_as_uint(Ps[(r0    ) * PS_STRIDE + c0 + 4]);
            qa[mt][ks][3] = __float_as_uint(Ps[(r0 + 8) * PS_STRIDE + c0 + 4]);
        }
    }

    float o[2][8][4];
    float l[2][2];
#pragma unroll
    for (int mt = 0; mt < 2; mt++) {
        l[mt][0] = 0.f; l[mt][1] = 0.f;
#pragma unroll
        for (int nt = 0; nt < 8; nt++)
#pragma unroll
            for (int j = 0; j < 4; j++) o[mt][nt][j] = 0.f;
    }

    const float* kb0 = K + ((size_t)b * S_) * D_ + h * DK_;
    const float* vb0 = V + ((size_t)b * S_) * D_ + h * DK_;

    for (int kt = 0; kt < NKT; kt++) {
        // ---- load K tile (tf32) + V tile (tf32) ----
        const float* kb = kb0 + (size_t)(kt * 64) * D_;
        const float* vb = vb0 + (size_t)(kt * 64) * D_;
        for (int i = tid; i < 64 * 16; i += 128) {
            int r = i >> 4, c = (i & 15) << 2;
            float4 x = *(const float4*)(kb + (size_t)r * D_ + c);
            x.x = to_tf32(x.x); x.y = to_tf32(x.y);
            x.z = to_tf32(x.z); x.w = to_tf32(x.w);
            *(float4*)(Ks + r * KS_STRIDE + c) = x;
            float4 y = *(const float4*)(vb + (size_t)r * D_ + c);
            y.x = to_tf32(y.x); y.y = to_tf32(y.y);
            y.z = to_tf32(y.z); y.w = to_tf32(y.w);
            *(float4*)(Vs + r * VS_STRIDE + c) = y;
        }
        __syncthreads();

        // ---- MMA1 (S = Q K^T), n-tiles in pairs for 4-way accumulator ILP ----
#pragma unroll
        for (int nt0 = 0; nt0 < 8; nt0 += 2) {
            float c4[2][2][4];   // [np][mt][4]
#pragma unroll
            for (int np = 0; np < 2; np++)
#pragma unroll
                for (int mt = 0; mt < 2; mt++)
#pragma unroll
                    for (int j = 0; j < 4; j++) c4[np][mt][j] = 0.f;

#pragma unroll
            for (int ks = 0; ks < 8; ks++) {
                const float* kr0 = Ks + ((nt0    ) * 8 + g) * KS_STRIDE + ks * 8 + t;
                const float* kr1 = Ks + ((nt0 + 1) * 8 + g) * KS_STRIDE + ks * 8 + t;
                uint32_t b00 = __float_as_uint(kr0[0]);
                uint32_t b01 = __float_as_uint(kr0[4]);
                uint32_t b10 = __float_as_uint(kr1[0]);
                uint32_t b11 = __float_as_uint(kr1[4]);
                mma_tf32(c4[0][0], qa[0][ks], b00, b01);
                mma_tf32(c4[1][0], qa[0][ks], b10, b11);
                mma_tf32(c4[0][1], qa[1][ks], b00, b01);
                mma_tf32(c4[1][1], qa[1][ks], b10, b11);
            }
#pragma unroll
            for (int np = 0; np < 2; np++) {
                const int nt = nt0 + np;
#pragma unroll
                for (int mt = 0; mt < 2; mt++) {
                    float e0 = __expf(c4[np][mt][0]);
                    float e1 = __expf(c4[np][mt][1]);
                    float e2 = __expf(c4[np][mt][2]);
                    float e3 = __expf(c4[np][mt][3]);
                    l[mt][0] += e0 + e1;
                    l[mt][1] += e2 + e3;
                    const int r0  = warp * 32 + mt * 16 + g;
                    const int col = nt * 8 + 2 * t;
                    float2 p0 = make_float2(to_tf32(e0), to_tf32(e1));
                    float2 p1 = make_float2(to_tf32(e2), to_tf32(e3));
                    *(float2*)(Ps + (r0    ) * PS_STRIDE + col) = p0;
                    *(float2*)(Ps + (r0 + 8) * PS_STRIDE + col) = p1;
                }
            }
        }
        __syncwarp();   // warp reads back only its own P rows

        // ---- MMA2: O += P V  (ks outer so P A-frags load once) ----
#pragma unroll
        for (int ks = 0; ks < 8; ks++) {
            uint32_t pa[2][4];
#pragma unroll
            for (int mt = 0; mt < 2; mt++) {
                const int r0 = warp * 32 + mt * 16 + g;
                const int c0 = ks * 8 + t;
                pa[mt][0] = __float_as_uint(Ps[(r0    ) * PS_STRIDE + c0    ]);
                pa[mt][1] = __float_as_uint(Ps[(r0 + 8) * PS_STRIDE + c0    ]);
                pa[mt][2] = __float_as_uint(Ps[(r0    ) * PS_STRIDE + c0 + 4]);
                pa[mt][3] = __float_as_uint(Ps[(r0 + 8) * PS_STRIDE + c0 + 4]);
            }
#pragma unroll
            for (int nt = 0; nt < 8; nt++) {
                uint32_t b0v = __float_as_uint(Vs[(ks * 8 + t    ) * VS_STRIDE + nt * 8 + g]);
                uint32_t b1v = __float_as_uint(Vs[(ks * 8 + t + 4) * VS_STRIDE + nt * 8 + g]);
                mma_tf32(o[0][nt], pa[0], b0v, b1v);
                mma_tf32(o[1][nt], pa[1], b0v, b1v);
            }
        }
        __syncthreads();   // before next tile's loads overwrite Ks/Vs
    }

    // ---- final row-sum reduce (quad) + normalize + store ----
    float inv[2][2];
#pragma unroll
    for (int mt = 0; mt < 2; mt++)
#pragma unroll
        for (int r = 0; r < 2; r++) {
            float v = l[mt][r];
            v += __shfl_xor_sync(0xffffffffu, v, 1);
            v += __shfl_xor_sync(0xffffffffu, v, 2);
            inv[mt][r] = 1.f / v;
        }

#pragma unroll
    for (int mt = 0; mt < 2; mt++) {
        const int row0 = qt * 128 + warp * 32 + mt * 16 + g;
        float* ob = g_attn + ((size_t)(b * S_ + row0)) * D_ + h * DK_;
#pragma unroll
        for (int nt = 0; nt < 8; nt++) {
            const int col = nt * 8 + 2 * t;
            float2 r0 = make_float2(o[mt][nt][0] * inv[mt][0],
                                    o[mt][nt][1] * inv[mt][0]);
            float2 r1 = make_float2(o[mt][nt][2] * inv[mt][1],
                                    o[mt][nt][3] * inv[mt][1]);
            *(float2*)(ob + col)          = r0;
            *(float2*)(ob + 8 * D_ + col) = r1;
        }
    }
}

// ---------------------------------------------------------------------------
// Projection via tf32 MMA: out[8192,512] = g_attn @ W + b.
// CTA tile 128x64, 4 warps (warp = 32 rows, 2 m-tiles), k-chunks of 64.
// ---------------------------------------------------------------------------
#define AS_STRIDE 68
#define WS_STRIDE 72
#define PROJ_SMEM_FLOATS (128 * AS_STRIDE + 64 * WS_STRIDE)

__global__ __launch_bounds__(128, 4)
void proj_kernel(const float* __restrict__ W,
                 const float* __restrict__ bias,
                 float* __restrict__ out)
{
    extern __shared__ float smem[];
    float* As = smem;                     // [128][68]
    float* Ws = smem + 128 * AS_STRIDE;   // [64][72]

    const int tid  = threadIdx.x;
    const int warp = tid >> 5;
    const int lane = tid & 31;
    const int g    = lane >> 2;
    const int t    = lane & 3;
    const int nb   = blockIdx.x;   // 0..7  (64-col tile)
    const int mb   = blockIdx.y;   // 0..63 (128-row tile)

    float o[2][8][4];
#pragma unroll
    for (int mt = 0; mt < 2; mt++)
#pragma unroll
        for (int nt = 0; nt < 8; nt++)
#pragma unroll
            for (int j = 0; j < 4; j++) o[mt][nt][j] = 0.f;

    const float* abase = g_attn + (size_t)mb * 128 * D_;

    for (int k0 = 0; k0 < D_; k0 += 64) {
        // A tile 128x64 (tf32 RN)
        for (int i = tid; i < 128 * 16; i += 128) {
            int r = i >> 4, c = (i & 15) << 2;
            float4 x = *(const float4*)(abase + (size_t)r * D_ + k0 + c);
            x.x = to_tf32(x.x); x.y = to_tf32(x.y);
            x.z = to_tf32(x.z); x.w = to_tf32(x.w);
            *(float4*)(As + r * AS_STRIDE + c) = x;
        }
        // W tile 64x64 (tf32 RN)
        for (int i = tid; i < 64 * 16; i += 128) {
            int r = i >> 4, c = (i & 15) << 2;
            float4 x = *(const float4*)(W + (size_t)(k0 + r) * D_ + nb * 64 + c);
            x.x = to_tf32(x.x); x.y = to_tf32(x.y);
            x.z = to_tf32(x.z); x.w = to_tf32(x.w);
            *(float4*)(Ws + r * WS_STRIDE + c) = x;
        }
        __syncthreads();

#pragma unroll
        for (int ks = 0; ks < 8; ks++) {
            uint32_t a[2][4];
#pragma unroll
            for (int mt = 0; mt < 2; mt++) {
                const int r0 = warp * 32 + mt * 16 + g;
                const int c0 = ks * 8 + t;
                a[mt][0] = __float_as_uint(As[(r0    ) * AS_STRIDE + c0    ]);
                a[mt][1] = __float_as_uint(As[(r0 + 8) * AS_STRIDE + c0    ]);
                a[mt][2] = __float_as_uint(As[(r0    ) * AS_STRIDE + c0 + 4]);
                a[mt][3] = __float_as_uint(As[(r0 + 8) * AS_STRIDE + c0 + 4]);
            }
#pragma unroll
            for (int nt = 0; nt < 8; nt++) {
                uint32_t b0v = __float_as_uint(Ws[(ks * 8 + t    ) * WS_STRIDE + nt * 8 + g]);
                uint32_t b1v = __float_as_uint(Ws[(ks * 8 + t + 4) * WS_STRIDE + nt * 8 + g]);
                mma_tf32(o[0][nt], a[0], b0v, b1v);
                mma_tf32(o[1][nt], a[1], b0v, b1v);
            }
        }
        __syncthreads();
    }

    // ---- epilogue: + bias, store ----
#pragma unroll
    for (int mt = 0; mt < 2; mt++) {
        const int row0 = mb * 128 + warp * 32 + mt * 16 + g;
        float* ob = out + (size_t)row0 * D_ + nb * 64;
#pragma unroll
        for (int nt = 0; nt < 8; nt++) {
            const int col = nt * 8 + 2 * t;
            float2 bb = *(const float2*)(bias + nb * 64 + col);
            float2 r0 = make_float2(o[mt][nt][0] + bb.x, o[mt][nt][1] + bb.y);
            float2 r1 = make_float2(o[mt][nt][2] + bb.x, o[mt][nt][3] + bb.y);
            *(float2*)(ob + col)          = r0;
            *(float2*)(ob + 8 * D_ + col) = r1;
        }
    }
}

extern "C" void kernel_launch(void* const* d_in, const int* in_sizes, int n_in,
                              void* d_out, int out_size)
{
    (void)in_sizes; (void)n_in; (void)out_size;
    const float* Q    = (const float*)d_in[0];
    const float* K    = (const float*)d_in[1];
    const float* V    = (const float*)d_in[2];
    const float* W    = (const float*)d_in[3];
    const float* bias = (const float*)d_in[4];
    float* out = (float*)d_out;

    const int attn_smem = SMEM_FLOATS * sizeof(float);
    const int proj_smem = PROJ_SMEM_FLOATS * sizeof(float);
    cudaFuncSetAttribute(attn_kernel, cudaFuncAttributeMaxDynamicSharedMemorySize,
                         attn_smem);
    cudaFuncSetAttribute(proj_kernel, cudaFuncAttributeMaxDynamicSharedMemorySize,
                         proj_smem);

    attn_kernel<<<dim3(S_ / 128, B_ * H_), 128, attn_smem>>>(Q, K, V);
    proj_kernel<<<dim3(D_ / 64, (B_ * S_) / 128), 128, proj_smem>>>(W, bias, out);
}

// round 9
// speedup vs baseline: 1.5400x; 1.5400x over previous
#include <cuda_runtime.h>
#include <cstdint>
#include <cstddef>

#define B_  2
#define S_  4096
#define D_  512
#define H_  8
#define DK_ 64

// Scratch for pre-projection attention output (alloc-free rule).
__device__ float g_attn[(size_t)B_ * S_ * D_];

__device__ __forceinline__ float to_tf32(float x) {
    float r;
    asm("cvt.rna.tf32.f32 %0, %1;" : "=f"(r) : "f"(x));
    return r;
}
__device__ __forceinline__ uint32_t smem_u32(const void* p) {
    uint32_t a;
    asm("{ .reg .u64 t; cvta.to.shared.u64 t, %1; cvt.u32.u64 %0, t; }"
        : "=r"(a) : "l"(p));
    return a;
}

// D = A*B + D, tf32 m16n8k8 (base sm_103-legal; runs on tensor pipe).
__device__ __forceinline__ void mma_tf32(float c[4], const uint32_t a[4],
                                         uint32_t b0, uint32_t b1) {
    asm volatile(
        "mma.sync.aligned.m16n8k8.row.col.f32.tf32.tf32.f32 "
        "{%0,%1,%2,%3}, {%4,%5,%6,%7}, {%8,%9}, {%0,%1,%2,%3};"
        : "+f"(c[0]), "+f"(c[1]), "+f"(c[2]), "+f"(c[3])
        : "r"(a[0]), "r"(a[1]), "r"(a[2]), "r"(a[3]), "r"(b0), "r"(b1));
}

#define CP_ASYNC16(saddr, gptr) \
    asm volatile("cp.async.cg.shared.global [%0], [%1], 16;" \
                 :: "r"(saddr), "l"(gptr))
#define CP_ASYNC_COMMIT() asm volatile("cp.async.commit_group;" ::: "memory")
#define CP_ASYNC_WAIT0()  asm volatile("cp.async.wait_group 0;" ::: "memory")

// Strides (floats), conflict-free for the fragment patterns:
// K/P stride 68 -> bank = (4g+t) distinct; V/W stride 72 -> bank = (8t+g) distinct.
#define KS_STRIDE 68
#define VS_STRIDE 72
#define PS_STRIDE 68
// Ks [64][68] + Vs double-buffer 2x[64][72] + Ps [128][68]
#define SMEM_FLOATS (64 * KS_STRIDE + 2 * 64 * VS_STRIDE + 128 * PS_STRIDE)

#define NKT (S_ / 64)

// ---------------------------------------------------------------------------
// tf32 warp-MMA flash attention (no-max softmax, O resident in registers),
// K-tile software-pipelined through registers, V-tile through cp.async.
// CTA = (b, h, 128-query tile). 4 warps; warp owns 32 query rows (2 m-tiles).
// ---------------------------------------------------------------------------
__global__ __launch_bounds__(128, 2)
void attn_kernel(const float* __restrict__ Q,
                 const float* __restrict__ K,
                 const float* __restrict__ V)
{
    extern __shared__ float smem[];
    float* Ks  = smem;                                       // [64][68]
    float* Vs0 = smem + 64 * KS_STRIDE;                      // [64][72] x2
    float* Ps  = smem + 64 * KS_STRIDE + 2 * 64 * VS_STRIDE; // [128][68]
    const uint32_t vs_base = smem_u32(Vs0);

    const int tid  = threadIdx.x;
    const int warp = tid >> 5;
    const int lane = tid & 31;
    const int g    = lane >> 2;
    const int t    = lane & 3;
    const int qt   = blockIdx.x;  // 0..31
    const int bh   = blockIdx.y;  // 0..15
    const int b    = bh >> 3, h = bh & 7;

    // ---- stage Q tile into Ps (scaled 1/8, tf32 RN), then to frags ----
    const float* qb = Q + ((size_t)(b * S_ + qt * 128)) * D_ + h * DK_;
    for (int i = tid; i < 128 * 16; i += 128) {
        int r = i >> 4, c = (i & 15) << 2;
        float4 x = *(const float4*)(qb + (size_t)r * D_ + c);
        x.x = to_tf32(x.x * 0.125f);
        x.y = to_tf32(x.y * 0.125f);
        x.z = to_tf32(x.z * 0.125f);
        x.w = to_tf32(x.w * 0.125f);
        *(float4*)(Ps + r * PS_STRIDE + c) = x;
    }
    __syncthreads();

    uint32_t qa[2][8][4];   // Q A-fragments, resident all kernel
#pragma unroll
    for (int mt = 0; mt < 2; mt++) {
        const int r0 = warp * 32 + mt * 16 + g;
#pragma unroll
        for (int ks = 0; ks < 8; ks++) {
            const int c0 = ks * 8 + t;
            qa[mt][ks][0] = __float_as_uint(Ps[(r0    ) * PS_STRIDE + c0    ]);
            qa[mt][ks][1] = __float_as_uint(Ps[(r0 + 8) * PS_STRIDE + c0    ]);
            qa[mt][ks][2] = __float_as_uint(Ps[(r0    ) * PS_STRIDE + c0 + 4]);
            qa[mt][ks][3] = __float_as_uint(Ps[(r0 + 8) * PS_STRIDE + c0 + 4]);
        }
    }

    float o[2][8][4];
    float l[2][2];
#pragma unroll
    for (int mt = 0; mt < 2; mt++) {
        l[mt][0] = 0.f; l[mt][1] = 0.f;
#pragma unroll
        for (int nt = 0; nt < 8; nt++)
#pragma unroll
            for (int j = 0; j < 4; j++) o[mt][nt][j] = 0.f;
    }

    const float* kb0 = K + ((size_t)b * S_) * D_ + h * DK_;
    const float* vb0 = V + ((size_t)b * S_) * D_ + h * DK_;

    // ---- preload tile 0: K (tf32 RN) into Ks, V raw into Vs[0] ----
    {
        const int r = tid >> 4, c = (tid & 15) << 2;  // 8 strided iters
#pragma unroll
        for (int ii = 0; ii < 8; ii++) {
            int rr = r + ii * 8;
            float4 x = *(const float4*)(kb0 + (size_t)rr * D_ + c);
            x.x = to_tf32(x.x); x.y = to_tf32(x.y);
            x.z = to_tf32(x.z); x.w = to_tf32(x.w);
            *(float4*)(Ks + rr * KS_STRIDE + c) = x;
            float4 y = *(const float4*)(vb0 + (size_t)rr * D_ + c);
            *(float4*)(Vs0 + rr * VS_STRIDE + c) = y;
        }
    }
    __syncthreads();

    const int pr = tid >> 4;            // prefetch row base
    const int pc = (tid & 15) << 2;     // prefetch col

    for (int kt = 0; kt < NKT; kt++) {
        const int nxt = kt + 1;
        float4 kreg[8];
        // ---- issue next-tile loads up front (hidden under MMA1) ----
        if (nxt < NKT) {
            const float* kb = kb0 + (size_t)(nxt * 64) * D_;
#pragma unroll
            for (int ii = 0; ii < 8; ii++)
                kreg[ii] = *(const float4*)(kb + (size_t)(pr + ii * 8) * D_ + pc);

            const float* vb = vb0 + (size_t)(nxt * 64) * D_;
            const uint32_t vdst = vs_base
                + (uint32_t)((nxt & 1) * 64 * VS_STRIDE) * 4u;
#pragma unroll
            for (int ii = 0; ii < 8; ii++) {
                int rr = pr + ii * 8;
                CP_ASYNC16(vdst + (uint32_t)(rr * VS_STRIDE + pc) * 4u,
                           vb + (size_t)rr * D_ + pc);
            }
            CP_ASYNC_COMMIT();
        }

        // ---- MMA1 (S = Q K^T), n-tiles paired for 4-way accumulator ILP ----
#pragma unroll
        for (int nt0 = 0; nt0 < 8; nt0 += 2) {
            float c4[2][2][4];   // [np][mt][4]
#pragma unroll
            for (int np = 0; np < 2; np++)
#pragma unroll
                for (int mt = 0; mt < 2; mt++)
#pragma unroll
                    for (int j = 0; j < 4; j++) c4[np][mt][j] = 0.f;

#pragma unroll
            for (int ks = 0; ks < 8; ks++) {
                const float* kr0 = Ks + ((nt0    ) * 8 + g) * KS_STRIDE + ks * 8 + t;
                const float* kr1 = Ks + ((nt0 + 1) * 8 + g) * KS_STRIDE + ks * 8 + t;
                uint32_t b00 = __float_as_uint(kr0[0]);
                uint32_t b01 = __float_as_uint(kr0[4]);
                uint32_t b10 = __float_as_uint(kr1[0]);
                uint32_t b11 = __float_as_uint(kr1[4]);
                mma_tf32(c4[0][0], qa[0][ks], b00, b01);
                mma_tf32(c4[1][0], qa[0][ks], b10, b11);
                mma_tf32(c4[0][1], qa[1][ks], b00, b01);
                mma_tf32(c4[1][1], qa[1][ks], b10, b11);
            }
#pragma unroll
            for (int np = 0; np < 2; np++) {
                const int nt = nt0 + np;
#pragma unroll
                for (int mt = 0; mt < 2; mt++) {
                    float e0 = __expf(c4[np][mt][0]);
                    float e1 = __expf(c4[np][mt][1]);
                    float e2 = __expf(c4[np][mt][2]);
                    float e3 = __expf(c4[np][mt][3]);
                    l[mt][0] += e0 + e1;
                    l[mt][1] += e2 + e3;
                    const int r0  = warp * 32 + mt * 16 + g;
                    const int col = nt * 8 + 2 * t;
                    float2 p0 = make_float2(to_tf32(e0), to_tf32(e1));
                    float2 p1 = make_float2(to_tf32(e2), to_tf32(e3));
                    *(float2*)(Ps + (r0    ) * PS_STRIDE + col) = p0;
                    *(float2*)(Ps + (r0 + 8) * PS_STRIDE + col) = p1;
                }
            }
        }
        __syncthreads();   // all warps done reading Ks (tile kt)

        // ---- store next K tile (tf32 RN) into Ks while MMA2 runs ----
        if (nxt < NKT) {
#pragma unroll
            for (int ii = 0; ii < 8; ii++) {
                float4 x = kreg[ii];
                x.x = to_tf32(x.x); x.y = to_tf32(x.y);
                x.z = to_tf32(x.z); x.w = to_tf32(x.w);
                *(float4*)(Ks + (pr + ii * 8) * KS_STRIDE + pc) = x;
            }
        }

        // ---- MMA2: O += P V  (ks outer so P A-frags load once) ----
        const float* Vc = Vs0 + (kt & 1) * 64 * VS_STRIDE;
#pragma unroll
        for (int ks = 0; ks < 8; ks++) {
            uint32_t pa[2][4];
#pragma unroll
            for (int mt = 0; mt < 2; mt++) {
                const int r0 = warp * 32 + mt * 16 + g;
                const int c0 = ks * 8 + t;
                pa[mt][0] = __float_as_uint(Ps[(r0    ) * PS_STRIDE + c0    ]);
                pa[mt][1] = __float_as_uint(Ps[(r0 + 8) * PS_STRIDE + c0    ]);
                pa[mt][2] = __float_as_uint(Ps[(r0    ) * PS_STRIDE + c0 + 4]);
                pa[mt][3] = __float_as_uint(Ps[(r0 + 8) * PS_STRIDE + c0 + 4]);
            }
#pragma unroll
            for (int nt = 0; nt < 8; nt++) {
                uint32_t b0v = __float_as_uint(Vc[(ks * 8 + t    ) * VS_STRIDE + nt * 8 + g]);
                uint32_t b1v = __float_as_uint(Vc[(ks * 8 + t + 4) * VS_STRIDE + nt * 8 + g]);
                mma_tf32(o[0][nt], pa[0], b0v, b1v);
                mma_tf32(o[1][nt], pa[1], b0v, b1v);
            }
        }
        CP_ASYNC_WAIT0();
        __syncthreads();   // next V tile landed; Ks stores visible; P reuse safe
    }

    // ---- final row-sum reduce (quad) + normalize + store ----
    float inv[2][2];
#pragma unroll
    for (int mt = 0; mt < 2; mt++)
#pragma unroll
        for (int r = 0; r < 2; r++) {
            float v = l[mt][r];
            v += __shfl_xor_sync(0xffffffffu, v, 1);
            v += __shfl_xor_sync(0xffffffffu, v, 2);
            inv[mt][r] = 1.f / v;
        }

#pragma unroll
    for (int mt = 0; mt < 2; mt++) {
        const int row0 = qt * 128 + warp * 32 + mt * 16 + g;
        float* ob = g_attn + ((size_t)(b * S_ + row0)) * D_ + h * DK_;
#pragma unroll
        for (int nt = 0; nt < 8; nt++) {
            const int col = nt * 8 + 2 * t;
            float2 r0 = make_float2(o[mt][nt][0] * inv[mt][0],
                                    o[mt][nt][1] * inv[mt][0]);
            float2 r1 = make_float2(o[mt][nt][2] * inv[mt][1],
                                    o[mt][nt][3] * inv[mt][1]);
            *(float2*)(ob + col)          = r0;
            *(float2*)(ob + 8 * D_ + col) = r1;
        }
    }
}

// ---------------------------------------------------------------------------
// Projection via tf32 MMA: out[8192,512] = g_attn @ W + b.
// CTA tile 128x64, 4 warps (warp = 32 rows, 2 m-tiles), k-chunks of 64.
// ---------------------------------------------------------------------------
#define AS_STRIDE 68
#define WS_STRIDE 72
#define PROJ_SMEM_FLOATS (128 * AS_STRIDE + 64 * WS_STRIDE)

__global__ __launch_bounds__(128, 4)
void proj_kernel(const float* __restrict__ W,
                 const float* __restrict__ bias,
                 float* __restrict__ out)
{
    extern __shared__ float smem[];
    float* As = smem;                     // [128][68]
    float* Ws = smem + 128 * AS_STRIDE;   // [64][72]

    const int tid  = threadIdx.x;
    const int warp = tid >> 5;
    const int lane = tid & 31;
    const int g    = lane >> 2;
    const int t    = lane & 3;
    const int nb   = blockIdx.x;   // 0..7  (64-col tile)
    const int mb   = blockIdx.y;   // 0..63 (128-row tile)

    float o[2][8][4];
#pragma unroll
    for (int mt = 0; mt < 2; mt++)
#pragma unroll
        for (int nt = 0; nt < 8; nt++)
#pragma unroll
            for (int j = 0; j < 4; j++) o[mt][nt][j] = 0.f;

    const float* abase = g_attn + (size_t)mb * 128 * D_;

    for (int k0 = 0; k0 < D_; k0 += 64) {
        for (int i = tid; i < 128 * 16; i += 128) {
            int r = i >> 4, c = (i & 15) << 2;
            float4 x = *(const float4*)(abase + (size_t)r * D_ + k0 + c);
            x.x = to_tf32(x.x); x.y = to_tf32(x.y);
            x.z = to_tf32(x.z); x.w = to_tf32(x.w);
            *(float4*)(As + r * AS_STRIDE + c) = x;
        }
        for (int i = tid; i < 64 * 16; i += 128) {
            int r = i >> 4, c = (i & 15) << 2;
            float4 x = *(const float4*)(W + (size_t)(k0 + r) * D_ + nb * 64 + c);
            x.x = to_tf32(x.x); x.y = to_tf32(x.y);
            x.z = to_tf32(x.z); x.w = to_tf32(x.w);
            *(float4*)(Ws + r * WS_STRIDE + c) = x;
        }
        __syncthreads();

#pragma unroll
        for (int ks = 0; ks < 8; ks++) {
            uint32_t a[2][4];
#pragma unroll
            for (int mt = 0; mt < 2; mt++) {
                const int r0 = warp * 32 + mt * 16 + g;
                const int c0 = ks * 8 + t;
                a[mt][0] = __float_as_uint(As[(r0    ) * AS_STRIDE + c0    ]);
                a[mt][1] = __float_as_uint(As[(r0 + 8) * AS_STRIDE + c0    ]);
                a[mt][2] = __float_as_uint(As[(r0    ) * AS_STRIDE + c0 + 4]);
                a[mt][3] = __float_as_uint(As[(r0 + 8) * AS_STRIDE + c0 + 4]);
            }
#pragma unroll
            for (int nt = 0; nt < 8; nt++) {
                uint32_t b0v = __float_as_uint(Ws[(ks * 8 + t    ) * WS_STRIDE + nt * 8 + g]);
                uint32_t b1v = __float_as_uint(Ws[(ks * 8 + t + 4) * WS_STRIDE + nt * 8 + g]);
                mma_tf32(o[0][nt], a[0], b0v, b1v);
                mma_tf32(o[1][nt], a[1], b0v, b1v);
            }
        }
        __syncthreads();
    }

#pragma unroll
    for (int mt = 0; mt < 2; mt++) {
        const int row0 = mb * 128 + warp * 32 + mt * 16 + g;
        float* ob = out + (size_t)row0 * D_ + nb * 64;
#pragma unroll
        for (int nt = 0; nt < 8; nt++) {
            const int col = nt * 8 + 2 * t;
            float2 bb = *(const float2*)(bias + nb * 64 + col);
            float2 r0 = make_float2(o[mt][nt][0] + bb.x, o[mt][nt][1] + bb.y);
            float2 r1 = make_float2(o[mt][nt][2] + bb.x, o[mt][nt][3] + bb.y);
            *(float2*)(ob + col)          = r0;
            *(float2*)(ob + 8 * D_ + col) = r1;
        }
    }
}

extern "C" void kernel_launch(void* const* d_in, const int* in_sizes, int n_in,
                              void* d_out, int out_size)
{
    (void)in_sizes; (void)n_in; (void)out_size;
    const float* Q    = (const float*)d_in[0];
    const float* K    = (const float*)d_in[1];
    const float* V    = (const float*)d_in[2];
    const float* W    = (const float*)d_in[3];
    const float* bias = (const float*)d_in[4];
    float* out = (float*)d_out;

    const int attn_smem = SMEM_FLOATS * sizeof(float);
    const int proj_smem = PROJ_SMEM_FLOATS * sizeof(float);
    cudaFuncSetAttribute(attn_kernel, cudaFuncAttributeMaxDynamicSharedMemorySize,
                         attn_smem);
    cudaFuncSetAttribute(proj_kernel, cudaFuncAttributeMaxDynamicSharedMemorySize,
                         proj_smem);

    attn_kernel<<<dim3(S_ / 128, B_ * H_), 128, attn_smem>>>(Q, K, V);
    proj_kernel<<<dim3(D_ / 64, (B_ * S_) / 128), 128, proj_smem>>>(W, bias, out);
}

// round 11
// speedup vs baseline: 1.5882x; 1.0313x over previous
#include <cuda_runtime.h>
#include <cstdint>
#include <cstddef>

#define B_  2
#define S_  4096
#define D_  512
#define H_  8
#define DK_ 64

// Scratch for pre-projection attention output (alloc-free rule).
__device__ float g_attn[(size_t)B_ * S_ * D_];

__device__ __forceinline__ float to_tf32(float x) {
    float r;
    asm("cvt.rna.tf32.f32 %0, %1;" : "=f"(r) : "f"(x));
    return r;
}
__device__ __forceinline__ uint32_t smem_u32(const void* p) {
    uint32_t a;
    asm("{ .reg .u64 t; cvta.to.shared.u64 t, %1; cvt.u32.u64 %0, t; }"
        : "=r"(a) : "l"(p));
    return a;
}

// D = A*B + D, tf32 m16n8k8 (base sm_103-legal; runs on tensor pipe).
__device__ __forceinline__ void mma_tf32(float c[4], const uint32_t a[4],
                                         uint32_t b0, uint32_t b1) {
    asm volatile(
        "mma.sync.aligned.m16n8k8.row.col.f32.tf32.tf32.f32 "
        "{%0,%1,%2,%3}, {%4,%5,%6,%7}, {%8,%9}, {%0,%1,%2,%3};"
        : "+f"(c[0]), "+f"(c[1]), "+f"(c[2]), "+f"(c[3])
        : "r"(a[0]), "r"(a[1]), "r"(a[2]), "r"(a[3]), "r"(b0), "r"(b1));
}

// x4 ldmatrix: 4 16-byte row-chunks per lane-group; for tf32 fragments each
// "m8n8.b16 matrix" is a 16B half-row of the b32 tile.
__device__ __forceinline__ void ldsm4(uint32_t r[4], uint32_t saddr) {
    asm volatile("ldmatrix.sync.aligned.m8n8.x4.shared.b16 {%0,%1,%2,%3}, [%4];"
        : "=r"(r[0]), "=r"(r[1]), "=r"(r[2]), "=r"(r[3]) : "r"(saddr));
}

#define CP_ASYNC16(saddr, gptr) \
    asm volatile("cp.async.cg.shared.global [%0], [%1], 16;" \
                 :: "r"(saddr), "l"(gptr))
#define CP_ASYNC_COMMIT() asm volatile("cp.async.commit_group;" ::: "memory")
#define CP_ASYNC_WAIT0()  asm volatile("cp.async.wait_group 0;" ::: "memory")

// Strides (floats): stride 68 -> ldmatrix row-chunks cover all 32 banks once;
// V stride 72 -> bank = (8t+g) distinct for the scalar fragment pattern.
#define KS_STRIDE 68
#define VS_STRIDE 72
#define PS_STRIDE 68
#define KBUF_FLOATS (64 * KS_STRIDE)
#define VBUF_FLOATS (64 * VS_STRIDE)
// Ks double [2][64][68] + Vs double [2][64][72] + Ps [128][68]
#define SMEM_FLOATS (2 * KBUF_FLOATS + 2 * VBUF_FLOATS + 128 * PS_STRIDE)

#define NKT (S_ / 64)

// ---------------------------------------------------------------------------
// tf32 warp-MMA flash attention (no-max softmax, O resident in registers).
// Both K and V double-buffered -> ONE __syncthreads per K-tile.
// K pipelined gmem->reg->smem; V pipelined via cp.async.
// CTA = (b, h, 128-query tile). 4 warps; warp owns 32 query rows (2 m-tiles).
// ---------------------------------------------------------------------------
__global__ __launch_bounds__(128, 2)
void attn_kernel(const float* __restrict__ Q,
                 const float* __restrict__ K,
                 const float* __restrict__ V)
{
    extern __shared__ float smem[];
    float* Ks0 = smem;                                     // [2][64][68]
    float* Vs0 = smem + 2 * KBUF_FLOATS;                   // [2][64][72]
    float* Ps  = smem + 2 * KBUF_FLOATS + 2 * VBUF_FLOATS; // [128][68]
    const uint32_t ks_addr = smem_u32(Ks0);
    const uint32_t vs_addr = smem_u32(Vs0);
    const uint32_t ps_addr = smem_u32(Ps);

    const int tid   = threadIdx.x;
    const int warp  = tid >> 5;
    const int lane  = tid & 31;
    const int g     = lane >> 2;
    const int t     = lane & 3;
    const int lane8 = lane & 7;
    const int lhi   = lane >> 3;          // 0..3 (ldmatrix matrix id)
    const int qt    = blockIdx.x;  // 0..31
    const int bh    = blockIdx.y;  // 0..15
    const int b     = bh >> 3, h = bh & 7;

    // ldmatrix per-lane base addresses (bytes)
    // K frag (B of MMA1): matrix m -> col chunk m*4 within a ks-pair block
    const uint32_t k_lm = ks_addr + (uint32_t)(lane8 * KS_STRIDE + lhi * 4) * 4u;
    // P frag (A of MMA2): matrix m -> row +8*(m&1), col +4*(m>>1)
    const uint32_t p_lm = ps_addr
        + (uint32_t)((warp * 32 + (lhi & 1) * 8 + lane8) * PS_STRIDE
                     + (lhi >> 1) * 4) * 4u;

    // ---- stage Q tile into Ps (scaled 1/8, tf32 RN), then to frags ----
    const float* qb = Q + ((size_t)(b * S_ + qt * 128)) * D_ + h * DK_;
    for (int i = tid; i < 128 * 16; i += 128) {
        int r = i >> 4, c = (i & 15) << 2;
        float4 x = *(const float4*)(qb + (size_t)r * D_ + c);
        x.x = to_tf32(x.x * 0.125f);
        x.y = to_tf32(x.y * 0.125f);
        x.z = to_tf32(x.z * 0.125f);
        x.w = to_tf32(x.w * 0.125f);
        *(float4*)(Ps + r * PS_STRIDE + c) = x;
    }
    __syncthreads();

    uint32_t qa[2][8][4];   // Q A-fragments, resident all kernel
#pragma unroll
    for (int mt = 0; mt < 2; mt++) {
        const int r0 = warp * 32 + mt * 16 + g;
#pragma unroll
        for (int ks = 0; ks < 8; ks++) {
            const int c0 = ks * 8 + t;
            qa[mt][ks][0] = __float_as_uint(Ps[(r0    ) * PS_STRIDE + c0    ]);
            qa[mt][ks][1] = __float_as_uint(Ps[(r0 + 8) * PS_STRIDE + c0    ]);
            qa[mt][ks][2] = __float_as_uint(Ps[(r0    ) * PS_STRIDE + c0 + 4]);
            qa[mt][ks][3] = __float_as_uint(Ps[(r0 + 8) * PS_STRIDE + c0 + 4]);
        }
    }

    float o[2][8][4];
    float l[2][2];
#pragma unroll
    for (int mt = 0; mt < 2; mt++) {
        l[mt][0] = 0.f; l[mt][1] = 0.f;
#pragma unroll
        for (int nt = 0; nt < 8; nt++)
#pragma unroll
            for (int j = 0; j < 4; j++) o[mt][nt][j] = 0.f;
    }

    const float* kb0 = K + ((size_t)b * S_) * D_ + h * DK_;
    const float* vb0 = V + ((size_t)b * S_) * D_ + h * DK_;

    const int pr = tid >> 4;            // staging row base (8 rows apart)
    const int pc = (tid & 15) << 2;     // staging col

    // ---- preload tile 0: K (tf32 RN) into Ks[0], V raw into Vs[0] ----
#pragma unroll
    for (int ii = 0; ii < 8; ii++) {
        int rr = pr + ii * 8;
        float4 x = *(const float4*)(kb0 + (size_t)rr * D_ + pc);
        x.x = to_tf32(x.x); x.y = to_tf32(x.y);
        x.z = to_tf32(x.z); x.w = to_tf32(x.w);
        *(float4*)(Ks0 + rr * KS_STRIDE + pc) = x;
        float4 y = *(const float4*)(vb0 + (size_t)rr * D_ + pc);
        *(float4*)(Vs0 + rr * VS_STRIDE + pc) = y;
    }
    __syncthreads();

    for (int kt = 0; kt < NKT; kt++) {
        const int cur = kt & 1, nb = cur ^ 1;
        const int nxt = kt + 1;
        float4 kreg[8];

        // ---- issue next-tile loads up front (hidden under MMA work) ----
        if (nxt < NKT) {
            const float* kb = kb0 + (size_t)(nxt * 64) * D_;
#pragma unroll
            for (int ii = 0; ii < 8; ii++)
                kreg[ii] = *(const float4*)(kb + (size_t)(pr + ii * 8) * D_ + pc);

            const float* vb = vb0 + (size_t)(nxt * 64) * D_;
            const uint32_t vdst = vs_addr + (uint32_t)(nb * VBUF_FLOATS) * 4u;
#pragma unroll
            for (int ii = 0; ii < 8; ii++) {
                int rr = pr + ii * 8;
                CP_ASYNC16(vdst + (uint32_t)(rr * VS_STRIDE + pc) * 4u,
                           vb + (size_t)rr * D_ + pc);
            }
            CP_ASYNC_COMMIT();
        }

        // ---- MMA1 (S = Q K^T): ldmatrix K-frags, 4-chain accumulator ILP ----
        const uint32_t klm = k_lm + (uint32_t)(cur * KBUF_FLOATS) * 4u;
#pragma unroll
        for (int nt0 = 0; nt0 < 8; nt0 += 2) {
            float c4[2][2][4];   // [np][mt][4]
#pragma unroll
            for (int np = 0; np < 2; np++)
#pragma unroll
                for (int mt = 0; mt < 2; mt++)
#pragma unroll
                    for (int j = 0; j < 4; j++) c4[np][mt][j] = 0.f;

#pragma unroll
            for (int p = 0; p < 4; p++) {   // ks pair = (2p, 2p+1)
                uint32_t f0[4], f1[4];
                ldsm4(f0, klm + (uint32_t)(((nt0    ) * 8) * KS_STRIDE + p * 16) * 4u);
                ldsm4(f1, klm + (uint32_t)(((nt0 + 1) * 8) * KS_STRIDE + p * 16) * 4u);
                mma_tf32(c4[0][0], qa[0][2 * p    ], f0[0], f0[1]);
                mma_tf32(c4[1][0], qa[0][2 * p    ], f1[0], f1[1]);
                mma_tf32(c4[0][1], qa[1][2 * p    ], f0[0], f0[1]);
                mma_tf32(c4[1][1], qa[1][2 * p    ], f1[0], f1[1]);
                mma_tf32(c4[0][0], qa[0][2 * p + 1], f0[2], f0[3]);
                mma_tf32(c4[1][0], qa[0][2 * p + 1], f1[2], f1[3]);
                mma_tf32(c4[0][1], qa[1][2 * p + 1], f0[2], f0[3]);
                mma_tf32(c4[1][1], qa[1][2 * p + 1], f1[2], f1[3]);
            }
#pragma unroll
            for (int np = 0; np < 2; np++) {
                const int nt = nt0 + np;
#pragma unroll
                for (int mt = 0; mt < 2; mt++) {
                    float e0 = __expf(c4[np][mt][0]);
                    float e1 = __expf(c4[np][mt][1]);
                    float e2 = __expf(c4[np][mt][2]);
                    float e3 = __expf(c4[np][mt][3]);
                    l[mt][0] += e0 + e1;
                    l[mt][1] += e2 + e3;
                    const int r0  = warp * 32 + mt * 16 + g;
                    const int col = nt * 8 + 2 * t;
                    float2 p0 = make_float2(to_tf32(e0), to_tf32(e1));
                    float2 p1 = make_float2(to_tf32(e2), to_tf32(e3));
                    *(float2*)(Ps + (r0    ) * PS_STRIDE + col) = p0;
                    *(float2*)(Ps + (r0 + 8) * PS_STRIDE + col) = p1;
                }
            }
        }
        __syncwarp();   // order P stores before this warp's ldmatrix reads

        // ---- store next K tile (tf32 RN) into the idle buffer ----
        if (nxt < NKT) {
            float* Kn = Ks0 + nb * KBUF_FLOATS;
#pragma unroll
            for (int ii = 0; ii < 8; ii++) {
                float4 x = kreg[ii];
                x.x = to_tf32(x.x); x.y = to_tf32(x.y);
                x.z = to_tf32(x.z); x.w = to_tf32(x.w);
                *(float4*)(Kn + (pr + ii * 8) * KS_STRIDE + pc) = x;
            }
        }

        // ---- MMA2: O += P V  (P via ldmatrix; V scalar, conflict-free) ----
        const float* Vc = Vs0 + cur * VBUF_FLOATS;
#pragma unroll
        for (int ks = 0; ks < 8; ks++) {
            uint32_t pa0[4], pa1[4];
            ldsm4(pa0, p_lm + (uint32_t)(ks * 8) * 4u);
            ldsm4(pa1, p_lm + (uint32_t)(16 * PS_STRIDE + ks * 8) * 4u);
#pragma unroll
            for (int nt = 0; nt < 8; nt++) {
                uint32_t b0v = __float_as_uint(Vc[(ks * 8 + t    ) * VS_STRIDE + nt * 8 + g]);
                uint32_t b1v = __float_as_uint(Vc[(ks * 8 + t + 4) * VS_STRIDE + nt * 8 + g]);
                mma_tf32(o[0][nt], pa0, b0v, b1v);
                mma_tf32(o[1][nt], pa1, b0v, b1v);
            }
        }
        CP_ASYNC_WAIT0();
        __syncthreads();   // single barrier: all buffers rotate safely
    }

    // ---- final row-sum reduce (quad) + normalize + store ----
    float inv[2][2];
#pragma unroll
    for (int mt = 0; mt < 2; mt++)
#pragma unroll
        for (int r = 0; r < 2; r++) {
            float v = l[mt][r];
            v += __shfl_xor_sync(0xffffffffu, v, 1);
            v += __shfl_xor_sync(0xffffffffu, v, 2);
            inv[mt][r] = 1.f / v;
        }

#pragma unroll
    for (int mt = 0; mt < 2; mt++) {
        const int row0 = qt * 128 + warp * 32 + mt * 16 + g;
        float* ob = g_attn + ((size_t)(b * S_ + row0)) * D_ + h * DK_;
#pragma unroll
        for (int nt = 0; nt < 8; nt++) {
            const int col = nt * 8 + 2 * t;
            float2 r0 = make_float2(o[mt][nt][0] * inv[mt][0],
                                    o[mt][nt][1] * inv[mt][0]);
            float2 r1 = make_float2(o[mt][nt][2] * inv[mt][1],
                                    o[mt][nt][3] * inv[mt][1]);
            *(float2*)(ob + col)          = r0;
            *(float2*)(ob + 8 * D_ + col) = r1;
        }
    }
}

// ---------------------------------------------------------------------------
// Projection via tf32 MMA: out[8192,512] = g_attn @ W + b.
// CTA tile 128x64, 4 warps (warp = 32 rows, 2 m-tiles), k-chunks of 64.
// ---------------------------------------------------------------------------
#define AS_STRIDE 68
#define WS_STRIDE 72
#define PROJ_SMEM_FLOATS (128 * AS_STRIDE + 64 * WS_STRIDE)

__global__ __launch_bounds__(128, 4)
void proj_kernel(const float* __restrict__ W,
                 const float* __restrict__ bias,
                 float* __restrict__ out)
{
    extern __shared__ float smem[];
    float* As = smem;                     // [128][68]
    float* Ws = smem + 128 * AS_STRIDE;   // [64][72]

    const int tid  = threadIdx.x;
    const int warp = tid >> 5;
    const int lane = tid & 31;
    const int g    = lane >> 2;
    const int t    = lane & 3;
    const int nb   = blockIdx.x;   // 0..7  (64-col tile)
    const int mb   = blockIdx.y;   // 0..63 (128-row tile)

    float o[2][8][4];
#pragma unroll
    for (int mt = 0; mt < 2; mt++)
#pragma unroll
        for (int nt = 0; nt < 8; nt++)
#pragma unroll
            for (int j = 0; j < 4; j++) o[mt][nt][j] = 0.f;

    const float* abase = g_attn + (size_t)mb * 128 * D_;

    for (int k0 = 0; k0 < D_; k0 += 64) {
        for (int i = tid; i < 128 * 16; i += 128) {
            int r = i >> 4, c = (i & 15) << 2;
            float4 x = *(const float4*)(abase + (size_t)r * D_ + k0 + c);
            x.x = to_tf32(x.x); x.y = to_tf32(x.y);
            x.z = to_tf32(x.z); x.w = to_tf32(x.w);
            *(float4*)(As + r * AS_STRIDE + c) = x;
        }
        for (int i = tid; i < 64 * 16; i += 128) {
            int r = i >> 4, c = (i & 15) << 2;
            float4 x = *(const float4*)(W + (size_t)(k0 + r) * D_ + nb * 64 + c);
            x.x = to_tf32(x.x); x.y = to_tf32(x.y);
            x.z = to_tf32(x.z); x.w = to_tf32(x.w);
            *(float4*)(Ws + r * WS_STRIDE + c) = x;
        }
        __syncthreads();

#pragma unroll
        for (int ks = 0; ks < 8; ks++) {
            uint32_t a[2][4];
#pragma unroll
            for (int mt = 0; mt < 2; mt++) {
                const int r0 = warp * 32 + mt * 16 + g;
                const int c0 = ks * 8 + t;
                a[mt][0] = __float_as_uint(As[(r0    ) * AS_STRIDE + c0    ]);
                a[mt][1] = __float_as_uint(As[(r0 + 8) * AS_STRIDE + c0    ]);
                a[mt][2] = __float_as_uint(As[(r0    ) * AS_STRIDE + c0 + 4]);
                a[mt][3] = __float_as_uint(As[(r0 + 8) * AS_STRIDE + c0 + 4]);
            }
#pragma unroll
            for (int nt = 0; nt < 8; nt++) {
                uint32_t b0v = __float_as_uint(Ws[(ks * 8 + t    ) * WS_STRIDE + nt * 8 + g]);
                uint32_t b1v = __float_as_uint(Ws[(ks * 8 + t + 4) * WS_STRIDE + nt * 8 + g]);
                mma_tf32(o[0][nt], a[0], b0v, b1v);
                mma_tf32(o[1][nt], a[1], b0v, b1v);
            }
        }
        __syncthreads();
    }

#pragma unroll
    for (int mt = 0; mt < 2; mt++) {
        const int row0 = mb * 128 + warp * 32 + mt * 16 + g;
        float* ob = out + (size_t)row0 * D_ + nb * 64;
#pragma unroll
        for (int nt = 0; nt < 8; nt++) {
            const int col = nt * 8 + 2 * t;
            float2 bb = *(const float2*)(bias + nb * 64 + col);
            float2 r0 = make_float2(o[mt][nt][0] + bb.x, o[mt][nt][1] + bb.y);
            float2 r1 = make_float2(o[mt][nt][2] + bb.x, o[mt][nt][3] + bb.y);
            *(float2*)(ob + col)          = r0;
            *(float2*)(ob + 8 * D_ + col) = r1;
        }
    }
}

extern "C" void kernel_launch(void* const* d_in, const int* in_sizes, int n_in,
                              void* d_out, int out_size)
{
    (void)in_sizes; (void)n_in; (void)out_size;
    const float* Q    = (const float*)d_in[0];
    const float* K    = (const float*)d_in[1];
    const float* V    = (const float*)d_in[2];
    const float* W    = (const float*)d_in[3];
    const float* bias = (const float*)d_in[4];
    float* out = (float*)d_out;

    const int attn_smem = SMEM_FLOATS * sizeof(float);       // 106496 B
    const int proj_smem = PROJ_SMEM_FLOATS * sizeof(float);
    cudaFuncSetAttribute(attn_kernel, cudaFuncAttributeMaxDynamicSharedMemorySize,
                         attn_smem);
    cudaFuncSetAttribute(proj_kernel, cudaFuncAttributeMaxDynamicSharedMemorySize,
                         proj_smem);

    attn_kernel<<<dim3(S_ / 128, B_ * H_), 128, attn_smem>>>(Q, K, V);
    proj_kernel<<<dim3(D_ / 64, (B_ * S_) / 128), 128, proj_smem>>>(W, bias, out);
}

// round 12
// speedup vs baseline: 1.6499x; 1.0388x over previous
#include <cuda_runtime.h>
#include <cstdint>
#include <cstddef>

#define B_  2
#define S_  4096
#define D_  512
#define H_  8
#define DK_ 64

// Scratch (alloc-free rule): attention output, and tf32-preconverted K.
__device__ float g_attn[(size_t)B_ * S_ * D_];
__device__ float g_kcvt[(size_t)B_ * S_ * D_];

__device__ __forceinline__ float to_tf32(float x) {
    float r;
    asm("cvt.rna.tf32.f32 %0, %1;" : "=f"(r) : "f"(x));
    return r;
}
__device__ __forceinline__ uint32_t smem_u32(const void* p) {
    uint32_t a;
    asm("{ .reg .u64 t; cvta.to.shared.u64 t, %1; cvt.u32.u64 %0, t; }"
        : "=r"(a) : "l"(p));
    return a;
}

// D = A*B + D, tf32 m16n8k8 (base sm_103-legal; runs on tensor pipe).
__device__ __forceinline__ void mma_tf32(float c[4], const uint32_t a[4],
                                         uint32_t b0, uint32_t b1) {
    asm volatile(
        "mma.sync.aligned.m16n8k8.row.col.f32.tf32.tf32.f32 "
        "{%0,%1,%2,%3}, {%4,%5,%6,%7}, {%8,%9}, {%0,%1,%2,%3};"
        : "+f"(c[0]), "+f"(c[1]), "+f"(c[2]), "+f"(c[3])
        : "r"(a[0]), "r"(a[1]), "r"(a[2]), "r"(a[3]), "r"(b0), "r"(b1));
}

// x4 ldmatrix: 4 16-byte row-chunks; for tf32 fragments each "m8n8.b16
// matrix" is a 16B half-row of the b32 tile.
__device__ __forceinline__ void ldsm4(uint32_t r[4], uint32_t saddr) {
    asm volatile("ldmatrix.sync.aligned.m8n8.x4.shared.b16 {%0,%1,%2,%3}, [%4];"
        : "=r"(r[0]), "=r"(r[1]), "=r"(r[2]), "=r"(r[3]) : "r"(saddr));
}

#define CP_ASYNC16(saddr, gptr) \
    asm volatile("cp.async.cg.shared.global [%0], [%1], 16;" \
                 :: "r"(saddr), "l"(gptr))
#define CP_ASYNC_COMMIT() asm volatile("cp.async.commit_group;" ::: "memory")
#define CP_ASYNC_WAIT0()  asm volatile("cp.async.wait_group 0;" ::: "memory")

// Strides (floats): stride 68 -> ldmatrix row-chunks cover all 32 banks once;
// V stride 72 -> bank = (8t+g) distinct for the scalar fragment pattern.
#define KS_STRIDE 68
#define VS_STRIDE 72
#define PS_STRIDE 68
#define KBUF_FLOATS (64 * KS_STRIDE)
#define VBUF_FLOATS (64 * VS_STRIDE)
#define SMEM_FLOATS (2 * KBUF_FLOATS + 2 * VBUF_FLOATS + 128 * PS_STRIDE)

#define NKT (S_ / 64)

// ---------------------------------------------------------------------------
// Prologue: K -> tf32(RN) once (was re-converted 32x inside the old loop).
// ---------------------------------------------------------------------------
__global__ __launch_bounds__(256)
void cvt_k_kernel(const float* __restrict__ K)
{
    size_t i = ((size_t)blockIdx.x * 256 + threadIdx.x);
    float4 x = ((const float4*)K)[i];
    x.x = to_tf32(x.x); x.y = to_tf32(x.y);
    x.z = to_tf32(x.z); x.w = to_tf32(x.w);
    ((float4*)g_kcvt)[i] = x;
}

// ---------------------------------------------------------------------------
// tf32 warp-MMA flash attention (no-max softmax, O resident in registers).
// K and V both double-buffered via cp.async -> ONE __syncthreads per tile.
// Row-sums computed by a ones-column MMA (bias-cancelling with the O MMA).
// CTA = (b, h, 128-query tile). 4 warps; warp owns 32 query rows (2 m-tiles).
// ---------------------------------------------------------------------------
__global__ __launch_bounds__(128, 2)
void attn_kernel(const float* __restrict__ Q,
                 const float* __restrict__ V)
{
    extern __shared__ float smem[];
    float* Ks0 = smem;                                     // [2][64][68]
    float* Vs0 = smem + 2 * KBUF_FLOATS;                   // [2][64][72]
    float* Ps  = smem + 2 * KBUF_FLOATS + 2 * VBUF_FLOATS; // [128][68]
    const uint32_t ks_addr = smem_u32(Ks0);
    const uint32_t vs_addr = smem_u32(Vs0);
    const uint32_t ps_addr = smem_u32(Ps);

    const int tid   = threadIdx.x;
    const int warp  = tid >> 5;
    const int lane  = tid & 31;
    const int g     = lane >> 2;
    const int t     = lane & 3;
    const int lane8 = lane & 7;
    const int lhi   = lane >> 3;
    const int qt    = blockIdx.x;  // 0..31
    const int bh    = blockIdx.y;  // 0..15
    const int b     = bh >> 3, h = bh & 7;

    // ldmatrix per-lane base addresses (bytes)
    const uint32_t k_lm = ks_addr + (uint32_t)(lane8 * KS_STRIDE + lhi * 4) * 4u;
    const uint32_t p_lm = ps_addr
        + (uint32_t)((warp * 32 + (lhi & 1) * 8 + lane8) * PS_STRIDE
                     + (lhi >> 1) * 4) * 4u;

    // Ones-column B operand for the row-sum MMA: B[k][0]=1, else 0.
    const uint32_t bone = (g == 0) ? 0x3f800000u : 0u;

    // ---- stage Q tile into Ps, scaled by (1/8)*log2(e), tf32 RN ----
    const float QSCALE = 0.125f * 1.4426950408889634f;
    const float* qb = Q + ((size_t)(b * S_ + qt * 128)) * D_ + h * DK_;
    for (int i = tid; i < 128 * 16; i += 128) {
        int r = i >> 4, c = (i & 15) << 2;
        float4 x = *(const float4*)(qb + (size_t)r * D_ + c);
        x.x = to_tf32(x.x * QSCALE);
        x.y = to_tf32(x.y * QSCALE);
        x.z = to_tf32(x.z * QSCALE);
        x.w = to_tf32(x.w * QSCALE);
        *(float4*)(Ps + r * PS_STRIDE + c) = x;
    }
    __syncthreads();

    uint32_t qa[2][8][4];   // Q A-fragments, resident all kernel
#pragma unroll
    for (int mt = 0; mt < 2; mt++) {
        const int r0 = warp * 32 + mt * 16 + g;
#pragma unroll
        for (int ks = 0; ks < 8; ks++) {
            const int c0 = ks * 8 + t;
            qa[mt][ks][0] = __float_as_uint(Ps[(r0    ) * PS_STRIDE + c0    ]);
            qa[mt][ks][1] = __float_as_uint(Ps[(r0 + 8) * PS_STRIDE + c0    ]);
            qa[mt][ks][2] = __float_as_uint(Ps[(r0    ) * PS_STRIDE + c0 + 4]);
            qa[mt][ks][3] = __float_as_uint(Ps[(r0 + 8) * PS_STRIDE + c0 + 4]);
        }
    }

    float o[2][8][4];
    float lacc[2][4];   // ones-column MMA accumulator (l in col 64 -> t==0)
#pragma unroll
    for (int mt = 0; mt < 2; mt++) {
#pragma unroll
        for (int j = 0; j < 4; j++) lacc[mt][j] = 0.f;
#pragma unroll
        for (int nt = 0; nt < 8; nt++)
#pragma unroll
            for (int j = 0; j < 4; j++) o[mt][nt][j] = 0.f;
    }

    const float* kb0 = g_kcvt + ((size_t)b * S_) * D_ + h * DK_;
    const float* vb0 = V      + ((size_t)b * S_) * D_ + h * DK_;

    const int pr = tid >> 4;            // staging row base (8 rows apart)
    const int pc = (tid & 15) << 2;     // staging col

    // ---- preload tile 0 via cp.async (K already tf32) ----
#pragma unroll
    for (int ii = 0; ii < 8; ii++) {
        int rr = pr + ii * 8;
        CP_ASYNC16(ks_addr + (uint32_t)(rr * KS_STRIDE + pc) * 4u,
                   kb0 + (size_t)rr * D_ + pc);
        CP_ASYNC16(vs_addr + (uint32_t)(rr * VS_STRIDE + pc) * 4u,
                   vb0 + (size_t)rr * D_ + pc);
    }
    CP_ASYNC_COMMIT();
    CP_ASYNC_WAIT0();
    __syncthreads();

    for (int kt = 0; kt < NKT; kt++) {
        const int cur = kt & 1, nb = cur ^ 1;
        const int nxt = kt + 1;

        // ---- issue next-tile cp.async up front (hidden under MMA work) ----
        if (nxt < NKT) {
            const float* kb = kb0 + (size_t)(nxt * 64) * D_;
            const float* vb = vb0 + (size_t)(nxt * 64) * D_;
            const uint32_t kdst = ks_addr + (uint32_t)(nb * KBUF_FLOATS) * 4u;
            const uint32_t vdst = vs_addr + (uint32_t)(nb * VBUF_FLOATS) * 4u;
#pragma unroll
            for (int ii = 0; ii < 8; ii++) {
                int rr = pr + ii * 8;
                CP_ASYNC16(kdst + (uint32_t)(rr * KS_STRIDE + pc) * 4u,
                           kb + (size_t)rr * D_ + pc);
                CP_ASYNC16(vdst + (uint32_t)(rr * VS_STRIDE + pc) * 4u,
                           vb + (size_t)rr * D_ + pc);
            }
            CP_ASYNC_COMMIT();
        }

        // ---- MMA1 (S = Q K^T): ldmatrix K-frags, 4-chain accumulator ILP ----
        const uint32_t klm = k_lm + (uint32_t)(cur * KBUF_FLOATS) * 4u;
#pragma unroll
        for (int nt0 = 0; nt0 < 8; nt0 += 2) {
            float c4[2][2][4];   // [np][mt][4]
#pragma unroll
            for (int np = 0; np < 2; np++)
#pragma unroll
                for (int mt = 0; mt < 2; mt++)
#pragma unroll
                    for (int j = 0; j < 4; j++) c4[np][mt][j] = 0.f;

#pragma unroll
            for (int p = 0; p < 4; p++) {   // ks pair = (2p, 2p+1)
                uint32_t f0[4], f1[4];
                ldsm4(f0, klm + (uint32_t)(((nt0    ) * 8) * KS_STRIDE + p * 16) * 4u);
                ldsm4(f1, klm + (uint32_t)(((nt0 + 1) * 8) * KS_STRIDE + p * 16) * 4u);
                mma_tf32(c4[0][0], qa[0][2 * p    ], f0[0], f0[1]);
                mma_tf32(c4[1][0], qa[0][2 * p    ], f1[0], f1[1]);
                mma_tf32(c4[0][1], qa[1][2 * p    ], f0[0], f0[1]);
                mma_tf32(c4[1][1], qa[1][2 * p    ], f1[0], f1[1]);
                mma_tf32(c4[0][0], qa[0][2 * p + 1], f0[2], f0[3]);
                mma_tf32(c4[1][0], qa[0][2 * p + 1], f1[2], f1[3]);
                mma_tf32(c4[0][1], qa[1][2 * p + 1], f0[2], f0[3]);
                mma_tf32(c4[1][1], qa[1][2 * p + 1], f1[2], f1[3]);
            }
            // ---- p = exp2(s), store raw fp32 (MMA truncation bias cancels
            //      between the O-MMA and the ones-MMA) ----
#pragma unroll
            for (int np = 0; np < 2; np++) {
                const int nt = nt0 + np;
#pragma unroll
                for (int mt = 0; mt < 2; mt++) {
                    float e0 = exp2f(c4[np][mt][0]);
                    float e1 = exp2f(c4[np][mt][1]);
                    float e2 = exp2f(c4[np][mt][2]);
                    float e3 = exp2f(c4[np][mt][3]);
                    const int r0  = warp * 32 + mt * 16 + g;
                    const int col = nt * 8 + 2 * t;
                    *(float2*)(Ps + (r0    ) * PS_STRIDE + col) = make_float2(e0, e1);
                    *(float2*)(Ps + (r0 + 8) * PS_STRIDE + col) = make_float2(e2, e3);
                }
            }
        }
        __syncwarp();   // order P stores before this warp's ldmatrix reads

        // ---- MMA2: O += P V, and lacc += P * ones (same P operand) ----
        const float* Vc = Vs0 + cur * VBUF_FLOATS;
#pragma unroll
        for (int ks = 0; ks < 8; ks++) {
            uint32_t pa0[4], pa1[4];
            ldsm4(pa0, p_lm + (uint32_t)(ks * 8) * 4u);
            ldsm4(pa1, p_lm + (uint32_t)(16 * PS_STRIDE + ks * 8) * 4u);
#pragma unroll
            for (int nt = 0; nt < 8; nt++) {
                uint32_t b0v = __float_as_uint(Vc[(ks * 8 + t    ) * VS_STRIDE + nt * 8 + g]);
                uint32_t b1v = __float_as_uint(Vc[(ks * 8 + t + 4) * VS_STRIDE + nt * 8 + g]);
                mma_tf32(o[0][nt], pa0, b0v, b1v);
                mma_tf32(o[1][nt], pa1, b0v, b1v);
            }
            mma_tf32(lacc[0], pa0, bone, bone);
            mma_tf32(lacc[1], pa1, bone, bone);
        }
        CP_ASYNC_WAIT0();
        __syncthreads();   // single barrier: all buffers rotate safely
    }

    // ---- extract l (col 0 of ones-tile -> t==0 lanes), broadcast, store ----
    float inv[2][2];
#pragma unroll
    for (int mt = 0; mt < 2; mt++) {
        float i0 = 1.f / lacc[mt][0];   // valid at t==0 (row g)
        float i1 = 1.f / lacc[mt][2];   // valid at t==0 (row g+8)
        inv[mt][0] = __shfl_sync(0xffffffffu, i0, lane & ~3);
        inv[mt][1] = __shfl_sync(0xffffffffu, i1, lane & ~3);
    }

#pragma unroll
    for (int mt = 0; mt < 2; mt++) {
        const int row0 = qt * 128 + warp * 32 + mt * 16 + g;
        float* ob = g_attn + ((size_t)(b * S_ + row0)) * D_ + h * DK_;
#pragma unroll
        for (int nt = 0; nt < 8; nt++) {
            const int col = nt * 8 + 2 * t;
            float2 r0 = make_float2(o[mt][nt][0] * inv[mt][0],
                                    o[mt][nt][1] * inv[mt][0]);
            float2 r1 = make_float2(o[mt][nt][2] * inv[mt][1],
                                    o[mt][nt][3] * inv[mt][1]);
            *(float2*)(ob + col)          = r0;
            *(float2*)(ob + 8 * D_ + col) = r1;
        }
    }
}

// ---------------------------------------------------------------------------
// Projection via tf32 MMA: out[8192,512] = g_attn @ W + b.
// ---------------------------------------------------------------------------
#define AS_STRIDE 68
#define WS_STRIDE 72
#define PROJ_SMEM_FLOATS (128 * AS_STRIDE + 64 * WS_STRIDE)

__global__ __launch_bounds__(128, 4)
void proj_kernel(const float* __restrict__ W,
                 const float* __restrict__ bias,
                 float* __restrict__ out)
{
    extern __shared__ float smem[];
    float* As = smem;                     // [128][68]
    float* Ws = smem + 128 * AS_STRIDE;   // [64][72]

    const int tid  = threadIdx.x;
    const int warp = tid >> 5;
    const int lane = tid & 31;
    const int g    = lane >> 2;
    const int t    = lane & 3;
    const int nb   = blockIdx.x;
    const int mb   = blockIdx.y;

    float o[2][8][4];
#pragma unroll
    for (int mt = 0; mt < 2; mt++)
#pragma unroll
        for (int nt = 0; nt < 8; nt++)
#pragma unroll
            for (int j = 0; j < 4; j++) o[mt][nt][j] = 0.f;

    const float* abase = g_attn + (size_t)mb * 128 * D_;

    for (int k0 = 0; k0 < D_; k0 += 64) {
        for (int i = tid; i < 128 * 16; i += 128) {
            int r = i >> 4, c = (i & 15) << 2;
            float4 x = *(const float4*)(abase + (size_t)r * D_ + k0 + c);
            x.x = to_tf32(x.x); x.y = to_tf32(x.y);
            x.z = to_tf32(x.z); x.w = to_tf32(x.w);
            *(float4*)(As + r * AS_STRIDE + c) = x;
        }
        for (int i = tid; i < 64 * 16; i += 128) {
            int r = i >> 4, c = (i & 15) << 2;
            float4 x = *(const float4*)(W + (size_t)(k0 + r) * D_ + nb * 64 + c);
            x.x = to_tf32(x.x); x.y = to_tf32(x.y);
            x.z = to_tf32(x.z); x.w = to_tf32(x.w);
            *(float4*)(Ws + r * WS_STRIDE + c) = x;
        }
        __syncthreads();

#pragma unroll
        for (int ks = 0; ks < 8; ks++) {
            uint32_t a[2][4];
#pragma unroll
            for (int mt = 0; mt < 2; mt++) {
                const int r0 = warp * 32 + mt * 16 + g;
                const int c0 = ks * 8 + t;
                a[mt][0] = __float_as_uint(As[(r0    ) * AS_STRIDE + c0    ]);
                a[mt][1] = __float_as_uint(As[(r0 + 8) * AS_STRIDE + c0    ]);
                a[mt][2] = __float_as_uint(As[(r0    ) * AS_STRIDE + c0 + 4]);
                a[mt][3] = __float_as_uint(As[(r0 + 8) * AS_STRIDE + c0 + 4]);
            }
#pragma unroll
            for (int nt = 0; nt < 8; nt++) {
                uint32_t b0v = __float_as_uint(Ws[(ks * 8 + t    ) * WS_STRIDE + nt * 8 + g]);
                uint32_t b1v = __float_as_uint(Ws[(ks * 8 + t + 4) * WS_STRIDE + nt * 8 + g]);
                mma_tf32(o[0][nt], a[0], b0v, b1v);
                mma_tf32(o[1][nt], a[1], b0v, b1v);
            }
        }
        __syncthreads();
    }

#pragma unroll
    for (int mt = 0; mt < 2; mt++) {
        const int row0 = mb * 128 + warp * 32 + mt * 16 + g;
        float* ob = out + (size_t)row0 * D_ + nb * 64;
#pragma unroll
        for (int nt = 0; nt < 8; nt++) {
            const int col = nt * 8 + 2 * t;
            float2 bb = *(const float2*)(bias + nb * 64 + col);
            float2 r0 = make_float2(o[mt][nt][0] + bb.x, o[mt][nt][1] + bb.y);
            float2 r1 = make_float2(o[mt][nt][2] + bb.x, o[mt][nt][3] + bb.y);
            *(float2*)(ob + col)          = r0;
            *(float2*)(ob + 8 * D_ + col) = r1;
        }
    }
}

extern "C" void kernel_launch(void* const* d_in, const int* in_sizes, int n_in,
                              void* d_out, int out_size)
{
    (void)in_sizes; (void)n_in; (void)out_size;
    const float* Q    = (const float*)d_in[0];
    const float* K    = (const float*)d_in[1];
    const float* V    = (const float*)d_in[2];
    const float* W    = (const float*)d_in[3];
    const float* bias = (const float*)d_in[4];
    float* out = (float*)d_out;

    const int attn_smem = SMEM_FLOATS * sizeof(float);       // 106496 B
    const int proj_smem = PROJ_SMEM_FLOATS * sizeof(float);
    cudaFuncSetAttribute(attn_kernel, cudaFuncAttributeMaxDynamicSharedMemorySize,
                         attn_smem);
    cudaFuncSetAttribute(proj_kernel, cudaFuncAttributeMaxDynamicSharedMemorySize,
                         proj_smem);

    cvt_k_kernel<<<(B_ * S_ * D_ / 4) / 256, 256>>>(K);
    attn_kernel<<<dim3(S_ / 128, B_ * H_), 128, attn_smem>>>(Q, V);
    proj_kernel<<<dim3(D_ / 64, (B_ * S_) / 128), 128, proj_smem>>>(W, bias, out);
}